// round 2
// baseline (speedup 1.0000x reference)
#include <cuda_runtime.h>
#include <cuda_bf16.h>
#include <math.h>

// Problem constants (fixed-shape problem)
#define BATCH 64
#define SEQ   512
#define HID   1024
#define INNER_ 1024
#define LRI   (0.01f / 1024.0f)
#define EPS_  1e-5f
#define CHUNK 64
#define NCHUNK (SEQ / CHUNK)

// ---------------- device scratch (static globals; no cudaMalloc allowed) ---
__device__ float g_Wd[HID * INNER_];          // W_init - Wt
__device__ float g_dbias[INNER_];             // b_init - bt
__device__ float g_D[(size_t)BATCH * SEQ * INNER_];   // D -> err -> z (gate preact)
__device__ float g_T[(size_t)BATCH * SEQ * INNER_];   // target -> silu(act)
__device__ float g_TTT[(size_t)BATCH * SEQ * HID];    // ttt
__device__ float g_C[(size_t)BATCH * SEQ * SEQ];      // Chat[b][t][s] = LRI*(x_t.x_s + 1)

// ---------------- prep: Wd = W_init - Wt, dbias = b_init - bt ---------------
__global__ void prep_kernel(const float* __restrict__ Wi, const float* __restrict__ Wt,
                            const float* __restrict__ bi, const float* __restrict__ bt) {
    int idx = blockIdx.x * blockDim.x + threadIdx.x;
    if (idx < HID * INNER_) g_Wd[idx] = Wi[idx] - Wt[idx];
    if (idx < INNER_) g_dbias[idx] = bi[idx] - bt[idx];
}

// ---------------- generic SGEMM: C = A(MxK,rm) * B(KxN,rm) [+bias] [+=C] ----
// Tile 128x128, BK=16, 256 threads, 8x8 per thread. All dims multiples of req.
__global__ __launch_bounds__(256)
void sgemm_nn(const float* __restrict__ A, const float* __restrict__ Bm,
              const float* __restrict__ bias, float* __restrict__ C,
              int M, int N, int K, int accum) {
    __shared__ float As[16][128];
    __shared__ float Bs[16][128];

    const int tid = threadIdx.x;
    const int tx = tid & 15;          // col group
    const int ty = tid >> 4;          // row group
    const int m0 = blockIdx.y * 128;
    const int n0 = blockIdx.x * 128;

    const int ar = tid >> 2;          // 0..63
    const int ac = (tid & 3) * 4;     // 0,4,8,12
    const int br = tid >> 5;          // 0..7
    const int bc = (tid & 31) * 4;    // 0..124

    float acc[8][8];
#pragma unroll
    for (int i = 0; i < 8; i++)
#pragma unroll
        for (int j = 0; j < 8; j++) acc[i][j] = 0.f;

    for (int k0 = 0; k0 < K; k0 += 16) {
        // load A 128x16 (transposed store)
        float4 a0 = *(const float4*)&A[(size_t)(m0 + ar) * K + k0 + ac];
        float4 a1 = *(const float4*)&A[(size_t)(m0 + ar + 64) * K + k0 + ac];
        As[ac + 0][ar] = a0.x; As[ac + 1][ar] = a0.y; As[ac + 2][ar] = a0.z; As[ac + 3][ar] = a0.w;
        As[ac + 0][ar + 64] = a1.x; As[ac + 1][ar + 64] = a1.y; As[ac + 2][ar + 64] = a1.z; As[ac + 3][ar + 64] = a1.w;
        // load B 16x128
        float4 b0 = *(const float4*)&Bm[(size_t)(k0 + br) * N + n0 + bc];
        float4 b1 = *(const float4*)&Bm[(size_t)(k0 + br + 8) * N + n0 + bc];
        *(float4*)&Bs[br][bc] = b0;
        *(float4*)&Bs[br + 8][bc] = b1;
        __syncthreads();

#pragma unroll
        for (int kk = 0; kk < 16; kk++) {
            float a[8], b[8];
#pragma unroll
            for (int j = 0; j < 8; j++) { a[j] = As[kk][ty * 8 + j]; b[j] = Bs[kk][tx * 8 + j]; }
#pragma unroll
            for (int i = 0; i < 8; i++)
#pragma unroll
                for (int j = 0; j < 8; j++) acc[i][j] += a[i] * b[j];
        }
        __syncthreads();
    }

#pragma unroll
    for (int i = 0; i < 8; i++) {
        size_t row = (size_t)(m0 + ty * 8 + i) * N;
#pragma unroll
        for (int j = 0; j < 8; j++) {
            int col = n0 + tx * 8 + j;
            float v = acc[i][j];
            if (bias) v += bias[col];
            if (accum) v += C[row + col];
            C[row + col] = v;
        }
    }
}

// ---------------- batched Gram: Chat[b][t][s] = LRI*(x[b,t].x[b,s] + 1) ----
__global__ __launch_bounds__(256)
void gram_nt(const float* __restrict__ X) {
    __shared__ float As[16][128];
    __shared__ float Bs[16][128];

    const int tid = threadIdx.x;
    const int tx = tid & 15;
    const int ty = tid >> 4;
    const int m0 = blockIdx.y * 128;
    const int n0 = blockIdx.x * 128;
    const int b = blockIdx.z;
    const float* A = X + (size_t)b * SEQ * HID;
    float* Cout = g_C + (size_t)b * SEQ * SEQ;

    const int ar = tid >> 2;
    const int ac = (tid & 3) * 4;

    float acc[8][8];
#pragma unroll
    for (int i = 0; i < 8; i++)
#pragma unroll
        for (int j = 0; j < 8; j++) acc[i][j] = 0.f;

    for (int k0 = 0; k0 < HID; k0 += 16) {
        float4 a0 = *(const float4*)&A[(size_t)(m0 + ar) * HID + k0 + ac];
        float4 a1 = *(const float4*)&A[(size_t)(m0 + ar + 64) * HID + k0 + ac];
        As[ac + 0][ar] = a0.x; As[ac + 1][ar] = a0.y; As[ac + 2][ar] = a0.z; As[ac + 3][ar] = a0.w;
        As[ac + 0][ar + 64] = a1.x; As[ac + 1][ar + 64] = a1.y; As[ac + 2][ar + 64] = a1.z; As[ac + 3][ar + 64] = a1.w;
        float4 c0 = *(const float4*)&A[(size_t)(n0 + ar) * HID + k0 + ac];
        float4 c1 = *(const float4*)&A[(size_t)(n0 + ar + 64) * HID + k0 + ac];
        Bs[ac + 0][ar] = c0.x; Bs[ac + 1][ar] = c0.y; Bs[ac + 2][ar] = c0.z; Bs[ac + 3][ar] = c0.w;
        Bs[ac + 0][ar + 64] = c1.x; Bs[ac + 1][ar + 64] = c1.y; Bs[ac + 2][ar + 64] = c1.z; Bs[ac + 3][ar + 64] = c1.w;
        __syncthreads();

#pragma unroll
        for (int kk = 0; kk < 16; kk++) {
            float a[8], bb[8];
#pragma unroll
            for (int j = 0; j < 8; j++) { a[j] = As[kk][ty * 8 + j]; bb[j] = Bs[kk][tx * 8 + j]; }
#pragma unroll
            for (int i = 0; i < 8; i++)
#pragma unroll
                for (int j = 0; j < 8; j++) acc[i][j] += a[i] * bb[j];
        }
        __syncthreads();
    }

#pragma unroll
    for (int i = 0; i < 8; i++) {
        size_t row = (size_t)(m0 + ty * 8 + i) * SEQ;
#pragma unroll
        for (int j = 0; j < 8; j++) {
            Cout[row + n0 + tx * 8 + j] = LRI * (acc[i][j] + 1.0f);
        }
    }
}

// ------------- chunked unit-lower-triangular solve (in place on g_D) -------
// err_t = D_t - sum_{s<t} Chat[t][s] * err_s ; chunk of 64 rows per launch.
__global__ __launch_bounds__(128)
void solve_chunk(int q) {
    const int b = blockIdx.y;
    const int i = blockIdx.x * 128 + threadIdx.x;
    __shared__ float sC[64][64];

    float* err = g_D + (size_t)b * SEQ * INNER_;
    const float* Crow = g_C + (size_t)b * SEQ * SEQ;
    const int t0 = q * CHUNK;

    float e[64];
#pragma unroll
    for (int t = 0; t < 64; t++) e[t] = err[(size_t)(t0 + t) * INNER_ + i];

    // history: subtract Chat[chunk, prev] @ err[prev]
    for (int sb = 0; sb < q; sb++) {
        for (int idx = threadIdx.x; idx < 64 * 64; idx += 128) {
            int tt = idx >> 6, ss = idx & 63;
            sC[tt][ss] = Crow[(size_t)(t0 + tt) * SEQ + sb * 64 + ss];
        }
        __syncthreads();
        for (int s = 0; s < 64; s++) {
            float ev = err[(size_t)(sb * 64 + s) * INNER_ + i];
#pragma unroll
            for (int t = 0; t < 64; t++) e[t] -= sC[t][s] * ev;
        }
        __syncthreads();
    }

    // diagonal block (strictly lower part used)
    for (int idx = threadIdx.x; idx < 64 * 64; idx += 128) {
        int tt = idx >> 6, ss = idx & 63;
        sC[tt][ss] = Crow[(size_t)(t0 + tt) * SEQ + t0 + ss];
    }
    __syncthreads();

#pragma unroll
    for (int t = 1; t < 64; t++) {
        float sum = 0.f;
#pragma unroll
        for (int s = 0; s < t; s++) sum += sC[t][s] * e[s];
        e[t] -= sum;
    }

#pragma unroll
    for (int t = 0; t < 64; t++) err[(size_t)(t0 + t) * INNER_ + i] = e[t];
}

// ---------------- act = silu(err + target) into g_T ------------------------
__global__ void silu_kernel() {
    size_t idx = (size_t)blockIdx.x * blockDim.x + threadIdx.x;
    float v = g_D[idx] + g_T[idx];                 // inner = err + target
    g_T[idx] = v / (1.0f + expf(-v));              // silu
}

// ---------------- gate + mix + layernorm -> out -----------------------------
__global__ __launch_bounds__(256)
void gate_ln(const float* __restrict__ x, const float* __restrict__ gamma,
             const float* __restrict__ beta, float* __restrict__ out) {
    const size_t row = blockIdx.x;
    const float* zr = g_D + row * HID;
    const float* tr = g_TTT + row * HID;
    const float* xr = x + row * HID;

    float y[4];
    float sum = 0.f, sumsq = 0.f;
#pragma unroll
    for (int k = 0; k < 4; k++) {
        int h = threadIdx.x + k * 256;
        float z = zr[h];
        float g = 1.0f / (1.0f + expf(-z));
        float v = g * tr[h] + (1.0f - g) * xr[h];
        y[k] = v;
        sum += v;
        sumsq += v * v;
    }

    // block reduce (8 warps)
    __shared__ float sa[8], sb[8];
#pragma unroll
    for (int o = 16; o > 0; o >>= 1) {
        sum += __shfl_down_sync(0xffffffffu, sum, o);
        sumsq += __shfl_down_sync(0xffffffffu, sumsq, o);
    }
    int w = threadIdx.x >> 5, l = threadIdx.x & 31;
    if (l == 0) { sa[w] = sum; sb[w] = sumsq; }
    __syncthreads();
    if (w == 0) {
        float a = (l < 8) ? sa[l] : 0.f;
        float bsum = (l < 8) ? sb[l] : 0.f;
#pragma unroll
        for (int o = 4; o > 0; o >>= 1) {
            a += __shfl_down_sync(0xffu, a, o);
            bsum += __shfl_down_sync(0xffu, bsum, o);
        }
        if (l == 0) { sa[0] = a; sb[0] = bsum; }
    }
    __syncthreads();
    float mu = sa[0] * (1.0f / HID);
    float var = sb[0] * (1.0f / HID) - mu * mu;
    float inv = rsqrtf(var + EPS_);

#pragma unroll
    for (int k = 0; k < 4; k++) {
        int h = threadIdx.x + k * 256;
        out[row * HID + h] = (y[k] - mu) * inv * gamma[h] + beta[h];
    }
}

// ---------------------------------------------------------------------------
extern "C" void kernel_launch(void* const* d_in, const int* in_sizes, int n_in,
                              void* d_out, int out_size) {
    const float* x      = (const float*)d_in[0];
    const float* W_init = (const float*)d_in[1];
    const float* b_init = (const float*)d_in[2];
    const float* Wt     = (const float*)d_in[3];
    const float* bt     = (const float*)d_in[4];
    const float* Wo     = (const float*)d_in[5];
    const float* bo     = (const float*)d_in[6];
    const float* Wg     = (const float*)d_in[7];
    const float* bg     = (const float*)d_in[8];
    const float* gamma  = (const float*)d_in[9];
    const float* beta   = (const float*)d_in[10];
    float* out = (float*)d_out;

    float *pD, *pT, *pTTT, *pWd, *pdb;
    cudaGetSymbolAddress((void**)&pD, g_D);
    cudaGetSymbolAddress((void**)&pT, g_T);
    cudaGetSymbolAddress((void**)&pTTT, g_TTT);
    cudaGetSymbolAddress((void**)&pWd, g_Wd);
    cudaGetSymbolAddress((void**)&pdb, g_dbias);

    const int M = BATCH * SEQ;          // 32768
    dim3 gemm_grid(HID / 128, M / 128); // (8, 256)

    // 0) Wd = W_init - Wt, dbias = b_init - bt
    prep_kernel<<<(HID * INNER_ + 255) / 256, 256>>>(W_init, Wt, b_init, bt);

    // 1) D = x @ Wd + dbias   (g_D)
    sgemm_nn<<<gemm_grid, 256>>>(x, pWd, pdb, pD, M, INNER_, HID, 0);
    // 2) T = x @ Wt + bt      (g_T)
    sgemm_nn<<<gemm_grid, 256>>>(x, Wt, bt, pT, M, INNER_, HID, 0);
    // 3) Chat = LRI * (X X^T + 1) per batch
    gram_nt<<<dim3(SEQ / 128, SEQ / 128, BATCH), 256>>>(x);
    // 4) triangular solve for err (in place on g_D), 8 sequential chunks
    for (int q = 0; q < NCHUNK; q++)
        solve_chunk<<<dim3(INNER_ / 128, BATCH), 128>>>(q);
    // 5) act = silu(err + T)  (into g_T)
    silu_kernel<<<(int)(((size_t)M * INNER_) / 256), 256>>>();
    // 6) ttt = act @ Wo + bo  (g_TTT)
    sgemm_nn<<<gemm_grid, 256>>>(pT, Wo, bo, pTTT, M, HID, INNER_, 0);
    // 7) z = x @ Wg_top + bg  (reuse g_D)
    sgemm_nn<<<gemm_grid, 256>>>(x, Wg, bg, pD, M, HID, HID, 0);
    // 8) z += ttt @ Wg_bot
    sgemm_nn<<<gemm_grid, 256>>>(pTTT, Wg + (size_t)HID * HID, nullptr, pD, M, HID, HID, 1);
    // 9) gate mix + layernorm -> out
    gate_ln<<<M, 256>>>(x, gamma, beta, out);
}

// round 5
// speedup vs baseline: 1.9987x; 1.9987x over previous
#include <cuda_runtime.h>
#include <cuda_bf16.h>
#include <math.h>
#include <stdint.h>

#define BATCH 64
#define SEQ   512
#define HID   1024
#define LRI   (0.01f / 1024.0f)
#define EPS_  1e-5f
#define CHUNK 64
#define NCHUNK (SEQ / CHUNK)
#define MTOT (BATCH * SEQ)

// ---------------- device scratch ----------------
__device__ __nv_bfloat16 g_xh[(size_t)MTOT * HID], g_xl[(size_t)MTOT * HID];
__device__ __nv_bfloat16 g_ach[(size_t)MTOT * HID], g_acl[(size_t)MTOT * HID];
__device__ __nv_bfloat16 g_tth[(size_t)MTOT * HID], g_ttl[(size_t)MTOT * HID];
__device__ __nv_bfloat16 g_wdh[HID * HID], g_wdl[HID * HID];
__device__ __nv_bfloat16 g_wth[HID * HID], g_wtl[HID * HID];
__device__ __nv_bfloat16 g_woh[HID * HID], g_wol[HID * HID];
__device__ __nv_bfloat16 g_wg1h[HID * HID], g_wg1l[HID * HID];
__device__ __nv_bfloat16 g_wg2h[HID * HID], g_wg2l[HID * HID];
__device__ float g_dbias[HID];
__device__ float g_D[(size_t)MTOT * HID];   // D -> err -> z
__device__ float g_T[(size_t)MTOT * HID];   // target
__device__ float g_TTT[(size_t)MTOT * HID]; // ttt fp32
__device__ float g_C[(size_t)BATCH * SEQ * SEQ];

// ---------------- PTX helpers (plain sm_80+ features only) ----------------
static __device__ __forceinline__ uint32_t s2u(const void* p) {
    uint32_t a;
    asm("{ .reg .u64 t; cvta.to.shared.u64 t, %1; cvt.u32.u64 %0, t; }" : "=r"(a) : "l"(p));
    return a;
}
#define CPA(dst, src) \
    asm volatile("cp.async.cg.shared.global [%0], [%1], 16;" :: "r"(dst), "l"(src))
#define CPCOMMIT() asm volatile("cp.async.commit_group;" ::: "memory")
#define CPWAIT1()  asm volatile("cp.async.wait_group 1;" ::: "memory")
#define LDSM4(r, addr) \
    asm volatile("ldmatrix.sync.aligned.m8n8.x4.shared.b16 {%0,%1,%2,%3}, [%4];" \
                 : "=r"((r)[0]), "=r"((r)[1]), "=r"((r)[2]), "=r"((r)[3]) : "r"(addr))
#define MMA(c, a, b0, b1) \
    asm volatile("mma.sync.aligned.m16n8k16.row.col.f32.bf16.bf16.f32 " \
                 "{%0,%1,%2,%3}, {%4,%5,%6,%7}, {%8,%9}, {%0,%1,%2,%3};" \
                 : "+f"((c)[0]), "+f"((c)[1]), "+f"((c)[2]), "+f"((c)[3]) \
                 : "r"((a)[0]), "r"((a)[1]), "r"((a)[2]), "r"((a)[3]), "r"(b0), "r"(b1))

// Per-stage smem: 4 buffers (Ah, Al, Bh, Bl), each 128 rows x 32 bf16,
// row padded to 80 bytes (5*16B -> conflict-free ldmatrix since gcd(5,8)=1).
#define BUF_BYTES 10240
#define STG_BYTES (4 * BUF_BYTES)
#define SMEM_BYTES (3 * STG_BYTES)

// ---------------- tensor GEMM: C[m][n] = sum_k A[m][k]*B[n][k] -------------
// split-bf16 3-pass. Optional second source (A2,B2) continues accumulation.
// mode 0: C = v (+bias). mode 1 (gram): C = LRI*(v+1), skip upper tiles.
// Coh/Col: optional bf16 hi/lo copy of output.
__global__ __launch_bounds__(256, 1)
void tgemm(const __nv_bfloat16* __restrict__ Ah, const __nv_bfloat16* __restrict__ Al,
           const __nv_bfloat16* __restrict__ Bh, const __nv_bfloat16* __restrict__ Bl,
           const __nv_bfloat16* __restrict__ A2h, const __nv_bfloat16* __restrict__ A2l,
           const __nv_bfloat16* __restrict__ B2h, const __nv_bfloat16* __restrict__ B2l,
           const float* __restrict__ bias, float* __restrict__ C,
           int lda, int ldb, int ldc,
           long long sA, long long sB, long long sC,
           int K1, int K2, int mode,
           __nv_bfloat16* __restrict__ Coh, __nv_bfloat16* __restrict__ Col) {
    if (mode == 1 && blockIdx.x > blockIdx.y) return;
    extern __shared__ char smem[];
    const uint32_t su = s2u(smem);
    const int tid = threadIdx.x;
    const int wid = tid >> 5, lane = tid & 31;
    const int wm = wid >> 2, wn = wid & 3;          // 2 x 4 warp grid, 64x32 per warp
    const int m0 = blockIdx.y * 128, n0 = blockIdx.x * 128;
    const size_t bz = blockIdx.z;

    const __nv_bfloat16* aH = Ah + bz * sA + (size_t)m0 * lda;
    const __nv_bfloat16* aL = Al + bz * sA + (size_t)m0 * lda;
    const __nv_bfloat16* bH = Bh + bz * sB + (size_t)n0 * ldb;
    const __nv_bfloat16* bL = Bl + bz * sB + (size_t)n0 * ldb;
    const __nv_bfloat16 *a2H = nullptr, *a2L = nullptr, *b2H = nullptr, *b2L = nullptr;
    if (K2) {
        a2H = A2h + (size_t)m0 * lda; a2L = A2l + (size_t)m0 * lda;
        b2H = B2h + (size_t)n0 * ldb; b2L = B2l + (size_t)n0 * ldb;
    }
    const int nc1 = K1 >> 5;
    const int NC = nc1 + (K2 >> 5);

    // ldmatrix per-lane base offsets (within a buffer), kk adds kk*32 bytes
    uint32_t aoff[4], boff[2];
#pragma unroll
    for (int mi = 0; mi < 4; mi++)
        aoff[mi] = (uint32_t)((wm * 64 + mi * 16 + (lane & 7) + ((lane >> 3) & 1) * 8) * 80
                              + ((lane >> 4) & 1) * 16);
#pragma unroll
    for (int g = 0; g < 2; g++)
        boff[g] = (uint32_t)((wn * 32 + g * 16 + (lane & 7) + ((lane >> 4) & 1) * 8) * 80
                             + ((lane >> 3) & 1) * 16);

    float acc[4][4][4];
#pragma unroll
    for (int i = 0; i < 4; i++)
#pragma unroll
        for (int j = 0; j < 4; j++)
#pragma unroll
            for (int r = 0; r < 4; r++) acc[i][j][r] = 0.f;

    auto load_chunk = [&](int stage, int c) {
        const __nv_bfloat16 *s0, *s1, *s2, *s3; int k0;
        if (c < nc1) { s0 = aH; s1 = aL; s2 = bH; s3 = bL; k0 = c << 5; }
        else         { s0 = a2H; s1 = a2L; s2 = b2H; s3 = b2L; k0 = (c - nc1) << 5; }
        const __nv_bfloat16* srcs[4] = { s0, s1, s2, s3 };
        const int lds[4] = { lda, lda, ldb, ldb };
        const uint32_t d0 = su + stage * STG_BYTES;
#pragma unroll
        for (int it = 0; it < 8; it++) {
            int t = it * 256 + tid;
            int buf = t >> 9, w = t & 511, row = w >> 2, ch = w & 3;
            const __nv_bfloat16* g = srcs[buf] + (size_t)row * lds[buf] + k0 + ch * 8;
            CPA(d0 + buf * BUF_BYTES + row * 80 + ch * 16, g);
        }
    };

    load_chunk(0, 0); CPCOMMIT();
    if (NC > 1) load_chunk(1, 1);
    CPCOMMIT();

    for (int c = 0; c < NC; c++) {
        CPWAIT1();
        __syncthreads();
        if (c + 2 < NC) load_chunk((c + 2) % 3, c + 2);
        CPCOMMIT();

        const uint32_t sb0 = su + (c % 3) * STG_BYTES;
#pragma unroll
        for (int kk = 0; kk < 2; kk++) {
            uint32_t ahf[4][4], alf[4][4], bhf[2][4], blf[2][4];
#pragma unroll
            for (int mi = 0; mi < 4; mi++) {
                LDSM4(ahf[mi], sb0 + aoff[mi] + kk * 32);
                LDSM4(alf[mi], sb0 + BUF_BYTES + aoff[mi] + kk * 32);
            }
#pragma unroll
            for (int g = 0; g < 2; g++) {
                LDSM4(bhf[g], sb0 + 2 * BUF_BYTES + boff[g] + kk * 32);
                LDSM4(blf[g], sb0 + 3 * BUF_BYTES + boff[g] + kk * 32);
            }
#pragma unroll
            for (int mi = 0; mi < 4; mi++)
#pragma unroll
                for (int nj = 0; nj < 4; nj++) {
                    const int g = nj >> 1, h = (nj & 1) * 2;
                    MMA(acc[mi][nj], ahf[mi], bhf[g][h], bhf[g][h + 1]);
                    MMA(acc[mi][nj], alf[mi], bhf[g][h], bhf[g][h + 1]);
                    MMA(acc[mi][nj], ahf[mi], blf[g][h], blf[g][h + 1]);
                }
        }
    }

    // epilogue: direct stores (float2 = 8B, 32B sectors OK)
    float* Cb = C + bz * sC;
    const int g4 = lane >> 2, tg = (lane & 3) * 2;
#pragma unroll
    for (int mi = 0; mi < 4; mi++)
#pragma unroll
        for (int nj = 0; nj < 4; nj++) {
            const int col = n0 + wn * 32 + nj * 8 + tg;
            float bv0 = 0.f, bv1 = 0.f;
            if (mode == 0 && bias) { bv0 = bias[col]; bv1 = bias[col + 1]; }
#pragma unroll
            for (int half = 0; half < 2; half++) {
                const int row = m0 + wm * 64 + mi * 16 + g4 + half * 8;
                float v0 = acc[mi][nj][half * 2], v1 = acc[mi][nj][half * 2 + 1];
                if (mode == 1) { v0 = LRI * (v0 + 1.f); v1 = LRI * (v1 + 1.f); }
                else { v0 += bv0; v1 += bv1; }
                const size_t gi = (size_t)row * ldc + col;
                *(float2*)&Cb[gi] = make_float2(v0, v1);
                if (Coh) {
                    __nv_bfloat16 h0 = __float2bfloat16(v0), h1 = __float2bfloat16(v1);
                    __nv_bfloat162 hp; hp.x = h0; hp.y = h1;
                    __nv_bfloat162 lp;
                    lp.x = __float2bfloat16(v0 - __bfloat162float(h0));
                    lp.y = __float2bfloat16(v1 - __bfloat162float(h1));
                    *(__nv_bfloat162*)&Coh[gi] = hp;
                    *(__nv_bfloat162*)&Col[gi] = lp;
                }
            }
        }
}

// ---------------- prep kernels ----------------
__global__ void wconv(const float* __restrict__ W, const float* __restrict__ Wsub,
                      __nv_bfloat16* __restrict__ oh, __nv_bfloat16* __restrict__ ol) {
    __shared__ float t[32][33];
    int bx = blockIdx.x * 32, by = blockIdx.y * 32;
    int tx = threadIdx.x, ty = threadIdx.y;
    for (int i = ty; i < 32; i += 8) {
        float v = W[(size_t)(by + i) * HID + bx + tx];
        if (Wsub) v -= Wsub[(size_t)(by + i) * HID + bx + tx];
        t[i][tx] = v;
    }
    __syncthreads();
    for (int i = ty; i < 32; i += 8) {
        float v = t[tx][i];
        size_t o = (size_t)(bx + i) * HID + by + tx;
        __nv_bfloat16 h = __float2bfloat16(v);
        oh[o] = h;
        ol[o] = __float2bfloat16(v - __bfloat162float(h));
    }
}

__global__ void cvt_split(const float* __restrict__ in, __nv_bfloat16* __restrict__ oh,
                          __nv_bfloat16* __restrict__ ol) {
    size_t i = (size_t)blockIdx.x * blockDim.x + threadIdx.x;
    float v = in[i];
    __nv_bfloat16 h = __float2bfloat16(v);
    oh[i] = h;
    ol[i] = __float2bfloat16(v - __bfloat162float(h));
}

__global__ void dbias_k(const float* __restrict__ bi, const float* __restrict__ bt) {
    int i = blockIdx.x * 256 + threadIdx.x;
    if (i < HID) g_dbias[i] = bi[i] - bt[i];
}

// ---------------- triangular solve (fp32) ----------------
__global__ __launch_bounds__(128)
void solve_chunk(int q) {
    const int b = blockIdx.y;
    const int i = blockIdx.x * 128 + threadIdx.x;
    __shared__ float sC[64][64];

    float* err = g_D + (size_t)b * SEQ * HID;
    const float* Crow = g_C + (size_t)b * SEQ * SEQ;
    const int t0 = q * CHUNK;

    float e[64];
#pragma unroll
    for (int t = 0; t < 64; t++) e[t] = err[(size_t)(t0 + t) * HID + i];

    for (int sbk = 0; sbk < q; sbk++) {
        for (int idx = threadIdx.x; idx < 64 * 64; idx += 128) {
            int tt = idx >> 6, ss = idx & 63;
            sC[tt][ss] = Crow[(size_t)(t0 + tt) * SEQ + sbk * 64 + ss];
        }
        __syncthreads();
        for (int s = 0; s < 64; s++) {
            float ev = err[(size_t)(sbk * 64 + s) * HID + i];
#pragma unroll
            for (int t = 0; t < 64; t++) e[t] -= sC[t][s] * ev;
        }
        __syncthreads();
    }

    for (int idx = threadIdx.x; idx < 64 * 64; idx += 128) {
        int tt = idx >> 6, ss = idx & 63;
        sC[tt][ss] = Crow[(size_t)(t0 + tt) * SEQ + t0 + ss];
    }
    __syncthreads();

#pragma unroll
    for (int t = 1; t < 64; t++) {
        float sum = 0.f;
#pragma unroll
        for (int s = 0; s < t; s++) sum += sC[t][s] * e[s];
        e[t] -= sum;
    }
#pragma unroll
    for (int t = 0; t < 64; t++) err[(size_t)(t0 + t) * HID + i] = e[t];
}

// ---------------- silu(err+target) -> bf16 hi/lo act ----------------
__global__ void silu_conv() {
    size_t i = (size_t)blockIdx.x * blockDim.x + threadIdx.x;
    float v = g_D[i] + g_T[i];
    float s = v / (1.0f + expf(-v));
    __nv_bfloat16 h = __float2bfloat16(s);
    g_ach[i] = h;
    g_acl[i] = __float2bfloat16(s - __bfloat162float(h));
}

// ---------------- gate + mix + layernorm ----------------
__global__ __launch_bounds__(256)
void gate_ln(const float* __restrict__ x, const float* __restrict__ gamma,
             const float* __restrict__ beta, float* __restrict__ out) {
    const size_t row = blockIdx.x;
    const float* zr = g_D + row * HID;
    const float* tr = g_TTT + row * HID;
    const float* xr = x + row * HID;

    float y[4];
    float sum = 0.f, sumsq = 0.f;
#pragma unroll
    for (int k = 0; k < 4; k++) {
        int h = threadIdx.x + k * 256;
        float z = zr[h];
        float g = 1.0f / (1.0f + expf(-z));
        float v = g * tr[h] + (1.0f - g) * xr[h];
        y[k] = v;
        sum += v;
        sumsq += v * v;
    }
    __shared__ float sa[8], sbm[8];
#pragma unroll
    for (int o = 16; o > 0; o >>= 1) {
        sum += __shfl_down_sync(0xffffffffu, sum, o);
        sumsq += __shfl_down_sync(0xffffffffu, sumsq, o);
    }
    int w = threadIdx.x >> 5, l = threadIdx.x & 31;
    if (l == 0) { sa[w] = sum; sbm[w] = sumsq; }
    __syncthreads();
    if (w == 0) {
        float a = (l < 8) ? sa[l] : 0.f;
        float bsum = (l < 8) ? sbm[l] : 0.f;
#pragma unroll
        for (int o = 4; o > 0; o >>= 1) {
            a += __shfl_down_sync(0xffu, a, o);
            bsum += __shfl_down_sync(0xffu, bsum, o);
        }
        if (l == 0) { sa[0] = a; sbm[0] = bsum; }
    }
    __syncthreads();
    float mu = sa[0] * (1.0f / HID);
    float var = sbm[0] * (1.0f / HID) - mu * mu;
    float inv = rsqrtf(var + EPS_);
#pragma unroll
    for (int k = 0; k < 4; k++) {
        int h = threadIdx.x + k * 256;
        out[row * HID + h] = (y[k] - mu) * inv * gamma[h] + beta[h];
    }
}

// ---------------------------------------------------------------------------
#define SYMP(T, p, s) T* p; { void* t_; cudaGetSymbolAddress(&t_, s); p = (T*)t_; }

extern "C" void kernel_launch(void* const* d_in, const int* in_sizes, int n_in,
                              void* d_out, int out_size) {
    const float* x      = (const float*)d_in[0];
    const float* W_init = (const float*)d_in[1];
    const float* b_init = (const float*)d_in[2];
    const float* Wt     = (const float*)d_in[3];
    const float* bt     = (const float*)d_in[4];
    const float* Wo     = (const float*)d_in[5];
    const float* bo     = (const float*)d_in[6];
    const float* Wg     = (const float*)d_in[7];
    const float* bg     = (const float*)d_in[8];
    const float* gamma  = (const float*)d_in[9];
    const float* beta   = (const float*)d_in[10];
    float* out = (float*)d_out;

    SYMP(__nv_bfloat16, pxh, g_xh);  SYMP(__nv_bfloat16, pxl, g_xl);
    SYMP(__nv_bfloat16, pah, g_ach); SYMP(__nv_bfloat16, pal, g_acl);
    SYMP(__nv_bfloat16, pth, g_tth); SYMP(__nv_bfloat16, ptl, g_ttl);
    SYMP(__nv_bfloat16, pwdh, g_wdh);  SYMP(__nv_bfloat16, pwdl, g_wdl);
    SYMP(__nv_bfloat16, pwth, g_wth);  SYMP(__nv_bfloat16, pwtl, g_wtl);
    SYMP(__nv_bfloat16, pwoh, g_woh);  SYMP(__nv_bfloat16, pwol, g_wol);
    SYMP(__nv_bfloat16, pwg1h, g_wg1h); SYMP(__nv_bfloat16, pwg1l, g_wg1l);
    SYMP(__nv_bfloat16, pwg2h, g_wg2h); SYMP(__nv_bfloat16, pwg2l, g_wg2l);
    SYMP(float, pdb, g_dbias);
    SYMP(float, pD, g_D); SYMP(float, pT, g_T); SYMP(float, pTTT, g_TTT);
    SYMP(float, pC, g_C);

    cudaFuncSetAttribute(tgemm, cudaFuncAttributeMaxDynamicSharedMemorySize, SMEM_BYTES);

    // prep: weight transposes/splits, dbias, x split
    dim3 wg(32, 32), wb(32, 8);
    wconv<<<wg, wb>>>(W_init, Wt, pwdh, pwdl);
    wconv<<<wg, wb>>>(Wt, nullptr, pwth, pwtl);
    wconv<<<wg, wb>>>(Wo, nullptr, pwoh, pwol);
    wconv<<<wg, wb>>>(Wg, nullptr, pwg1h, pwg1l);
    wconv<<<wg, wb>>>(Wg + (size_t)HID * HID, nullptr, pwg2h, pwg2l);
    dbias_k<<<4, 256>>>(b_init, bt);
    cvt_split<<<(unsigned)(((size_t)MTOT * HID) / 256), 256>>>(x, pxh, pxl);

    dim3 gmain(8, 256, 1);
    // 1) D = x @ (W_init - Wt) + (b_init - bt)
    tgemm<<<gmain, 256, SMEM_BYTES>>>(pxh, pxl, pwdh, pwdl, 0, 0, 0, 0, pdb, pD,
                                      HID, HID, HID, 0, 0, 0, HID, 0, 0, nullptr, nullptr);
    // 2) T = x @ Wt + bt
    tgemm<<<gmain, 256, SMEM_BYTES>>>(pxh, pxl, pwth, pwtl, 0, 0, 0, 0, bt, pT,
                                      HID, HID, HID, 0, 0, 0, HID, 0, 0, nullptr, nullptr);
    // 3) Chat = LRI*(X X^T + 1) per batch (lower tiles only)
    tgemm<<<dim3(4, 4, BATCH), 256, SMEM_BYTES>>>(pxh, pxl, pxh, pxl, 0, 0, 0, 0, nullptr, pC,
                                      HID, HID, SEQ, (long long)SEQ * HID, (long long)SEQ * HID,
                                      (long long)SEQ * SEQ, HID, 0, 1, nullptr, nullptr);
    // 4) triangular solve
    for (int q = 0; q < NCHUNK; q++)
        solve_chunk<<<dim3(HID / 128, BATCH), 128>>>(q);
    // 5) act = silu(err + T) -> bf16 hi/lo
    silu_conv<<<(unsigned)(((size_t)MTOT * HID) / 256), 256>>>();
    // 6) ttt = act @ Wo + bo (fp32 + bf16 split out)
    tgemm<<<gmain, 256, SMEM_BYTES>>>(pah, pal, pwoh, pwol, 0, 0, 0, 0, bo, pTTT,
                                      HID, HID, HID, 0, 0, 0, HID, 0, 0, pth, ptl);
    // 7) z = x @ Wg_top + ttt @ Wg_bot + bg (dual-source, K=2048)
    tgemm<<<gmain, 256, SMEM_BYTES>>>(pxh, pxl, pwg1h, pwg1l, pth, ptl, pwg2h, pwg2l, bg, pD,
                                      HID, HID, HID, 0, 0, 0, HID, HID, 0, nullptr, nullptr);
    // 8) gate mix + layernorm
    gate_ln<<<MTOT, 256>>>(x, gamma, beta, out);
}

// round 10
// speedup vs baseline: 3.3800x; 1.6911x over previous
#include <cuda_runtime.h>
#include <cuda_bf16.h>
#include <cuda_fp16.h>
#include <math.h>
#include <stdint.h>

#define BATCH 64
#define SEQ   512
#define HID   1024
#define LRI   (0.01f / 1024.0f)
#define EPS_  1e-5f
#define CHUNK 64
#define NCHUNK (SEQ / CHUNK)
#define MTOT (BATCH * SEQ)

// ---------------- device scratch ----------------
__device__ __half g_xh[(size_t)MTOT * HID];
__device__ __half g_ach[(size_t)MTOT * HID];
__device__ __half g_tth[(size_t)MTOT * HID];
__device__ __half g_wd[HID * HID];
__device__ __half g_wt[HID * HID];
__device__ __half g_wo[HID * HID];
__device__ __half g_wg1[HID * HID];
__device__ __half g_wg2[HID * HID];
__device__ float g_dbias[HID];
__device__ float g_D[(size_t)MTOT * HID];   // D -> err -> z
__device__ float g_T[(size_t)MTOT * HID];   // target
__device__ float g_TTT[(size_t)MTOT * HID]; // ttt fp32
__device__ float g_C[(size_t)BATCH * SEQ * SEQ];

// ---------------- PTX helpers (plain sm_80+ features only) ----------------
static __device__ __forceinline__ uint32_t s2u(const void* p) {
    uint32_t a;
    asm("{ .reg .u64 t; cvta.to.shared.u64 t, %1; cvt.u32.u64 %0, t; }" : "=r"(a) : "l"(p));
    return a;
}
#define CPA(dst, src) \
    asm volatile("cp.async.cg.shared.global [%0], [%1], 16;" :: "r"(dst), "l"(src))
#define CPCOMMIT() asm volatile("cp.async.commit_group;" ::: "memory")
#define CPWAIT1()  asm volatile("cp.async.wait_group 1;" ::: "memory")
#define LDSM4(r, addr) \
    asm volatile("ldmatrix.sync.aligned.m8n8.x4.shared.b16 {%0,%1,%2,%3}, [%4];" \
                 : "=r"((r)[0]), "=r"((r)[1]), "=r"((r)[2]), "=r"((r)[3]) : "r"(addr))
#define MMA(c, a, b0, b1) \
    asm volatile("mma.sync.aligned.m16n8k16.row.col.f32.f16.f16.f32 " \
                 "{%0,%1,%2,%3}, {%4,%5,%6,%7}, {%8,%9}, {%0,%1,%2,%3};" \
                 : "+f"((c)[0]), "+f"((c)[1]), "+f"((c)[2]), "+f"((c)[3]) \
                 : "r"((a)[0]), "r"((a)[1]), "r"((a)[2]), "r"((a)[3]), "r"(b0), "r"(b1))

// Per-stage smem: 2 buffers (A, B), each 128 rows x 32 halfs,
// row padded to 80 bytes (gcd(5,8)=1 -> conflict-free ldmatrix).
#define BUF_BYTES 10240
#define STG_BYTES (2 * BUF_BYTES)
#define SMEM_BYTES (3 * STG_BYTES)

// ---------------- tensor GEMM: C[m][n] = sum_k A[m][k]*B[n][k] -------------
// single-pass fp16, fp32 accumulate. Optional second source (A2,B2).
// mode 0: C = v (+bias). mode 1 (gram): C = LRI*(v+1), skip upper tiles.
// Coh: optional fp16 copy of output.
__global__ __launch_bounds__(256, 1)
void tgemm(const __half* __restrict__ Ah, const __half* __restrict__ Bh,
           const __half* __restrict__ A2h, const __half* __restrict__ B2h,
           const float* __restrict__ bias, float* __restrict__ C,
           int lda, int ldb, int ldc,
           long long sA, long long sB, long long sC,
           int K1, int K2, int mode,
           __half* __restrict__ Coh) {
    if (mode == 1 && blockIdx.x > blockIdx.y) return;
    extern __shared__ char smem[];
    const uint32_t su = s2u(smem);
    const int tid = threadIdx.x;
    const int wid = tid >> 5, lane = tid & 31;
    const int wm = wid >> 2, wn = wid & 3;          // 2 x 4 warp grid, 64x32 per warp
    const int m0 = blockIdx.y * 128, n0 = blockIdx.x * 128;
    const size_t bz = blockIdx.z;

    const __half* aH = Ah + bz * sA + (size_t)m0 * lda;
    const __half* bH = Bh + bz * sB + (size_t)n0 * ldb;
    const __half *a2H = nullptr, *b2H = nullptr;
    if (K2) {
        a2H = A2h + (size_t)m0 * lda;
        b2H = B2h + (size_t)n0 * ldb;
    }
    const int nc1 = K1 >> 5;
    const int NC = nc1 + (K2 >> 5);

    uint32_t aoff[4], boff[2];
#pragma unroll
    for (int mi = 0; mi < 4; mi++)
        aoff[mi] = (uint32_t)((wm * 64 + mi * 16 + (lane & 7) + ((lane >> 3) & 1) * 8) * 80
                              + ((lane >> 4) & 1) * 16);
#pragma unroll
    for (int g = 0; g < 2; g++)
        boff[g] = (uint32_t)((wn * 32 + g * 16 + (lane & 7) + ((lane >> 4) & 1) * 8) * 80
                             + ((lane >> 3) & 1) * 16);

    float acc[4][4][4];
#pragma unroll
    for (int i = 0; i < 4; i++)
#pragma unroll
        for (int j = 0; j < 4; j++)
#pragma unroll
            for (int r = 0; r < 4; r++) acc[i][j][r] = 0.f;

    auto load_chunk = [&](int stage, int c) {
        const __half *s0, *s1; int k0;
        if (c < nc1) { s0 = aH; s1 = bH; k0 = c << 5; }
        else         { s0 = a2H; s1 = b2H; k0 = (c - nc1) << 5; }
        const __half* srcs[2] = { s0, s1 };
        const int lds[2] = { lda, ldb };
        const uint32_t d0 = su + stage * STG_BYTES;
#pragma unroll
        for (int it = 0; it < 4; it++) {
            int t = it * 256 + tid;
            int buf = t >> 9, w = t & 511, row = w >> 2, ch = w & 3;
            const __half* g = srcs[buf] + (size_t)row * lds[buf] + k0 + ch * 8;
            CPA(d0 + buf * BUF_BYTES + row * 80 + ch * 16, g);
        }
    };

    load_chunk(0, 0); CPCOMMIT();
    if (NC > 1) load_chunk(1, 1);
    CPCOMMIT();

    for (int c = 0; c < NC; c++) {
        CPWAIT1();
        __syncthreads();
        if (c + 2 < NC) load_chunk((c + 2) % 3, c + 2);
        CPCOMMIT();

        const uint32_t sb0 = su + (c % 3) * STG_BYTES;
#pragma unroll
        for (int kk = 0; kk < 2; kk++) {
            uint32_t ahf[4][4], bhf[2][4];
#pragma unroll
            for (int mi = 0; mi < 4; mi++)
                LDSM4(ahf[mi], sb0 + aoff[mi] + kk * 32);
#pragma unroll
            for (int g = 0; g < 2; g++)
                LDSM4(bhf[g], sb0 + BUF_BYTES + boff[g] + kk * 32);
#pragma unroll
            for (int mi = 0; mi < 4; mi++)
#pragma unroll
                for (int nj = 0; nj < 4; nj++) {
                    const int g = nj >> 1, h = (nj & 1) * 2;
                    MMA(acc[mi][nj], ahf[mi], bhf[g][h], bhf[g][h + 1]);
                }
        }
    }

    // epilogue: direct stores
    float* Cb = C + bz * sC;
    const int g4 = lane >> 2, tg = (lane & 3) * 2;
#pragma unroll
    for (int mi = 0; mi < 4; mi++)
#pragma unroll
        for (int nj = 0; nj < 4; nj++) {
            const int col = n0 + wn * 32 + nj * 8 + tg;
            float bv0 = 0.f, bv1 = 0.f;
            if (mode == 0 && bias) { bv0 = bias[col]; bv1 = bias[col + 1]; }
#pragma unroll
            for (int half_ = 0; half_ < 2; half_++) {
                const int row = m0 + wm * 64 + mi * 16 + g4 + half_ * 8;
                float v0 = acc[mi][nj][half_ * 2], v1 = acc[mi][nj][half_ * 2 + 1];
                if (mode == 1) { v0 = LRI * (v0 + 1.f); v1 = LRI * (v1 + 1.f); }
                else { v0 += bv0; v1 += bv1; }
                const size_t gi = (size_t)row * ldc + col;
                *(float2*)&Cb[gi] = make_float2(v0, v1);
                if (Coh) {
                    __half2 hp;
                    hp.x = __float2half_rn(v0);
                    hp.y = __float2half_rn(v1);
                    *(__half2*)&Coh[gi] = hp;
                }
            }
        }
}

// ---------------- prep kernels ----------------
// transpose-convert weight [K][N] fp32 -> fp16 [N][K]; optional subtract
__global__ void wconv(const float* __restrict__ W, const float* __restrict__ Wsub,
                      __half* __restrict__ oh) {
    __shared__ float t[32][33];
    int bx = blockIdx.x * 32, by = blockIdx.y * 32;
    int tx = threadIdx.x, ty = threadIdx.y;
    for (int i = ty; i < 32; i += 8) {
        float v = W[(size_t)(by + i) * HID + bx + tx];
        if (Wsub) v -= Wsub[(size_t)(by + i) * HID + bx + tx];
        t[i][tx] = v;
    }
    __syncthreads();
    for (int i = ty; i < 32; i += 8)
        oh[(size_t)(bx + i) * HID + by + tx] = __float2half_rn(t[tx][i]);
}

__global__ void cvt_h(const float* __restrict__ in, __half* __restrict__ oh) {
    size_t i = ((size_t)blockIdx.x * blockDim.x + threadIdx.x) * 2;
    float2 v = *(const float2*)&in[i];
    __half2 h; h.x = __float2half_rn(v.x); h.y = __float2half_rn(v.y);
    *(__half2*)&oh[i] = h;
}

__global__ void dbias_k(const float* __restrict__ bi, const float* __restrict__ bt) {
    int i = blockIdx.x * 256 + threadIdx.x;
    if (i < HID) g_dbias[i] = bi[i] - bt[i];
}

// ---------------- triangular solve (fp32) ----------------
__global__ __launch_bounds__(128)
void solve_chunk(int q) {
    const int b = blockIdx.y;
    const int i = blockIdx.x * 128 + threadIdx.x;
    __shared__ float sC[64][64];

    float* err = g_D + (size_t)b * SEQ * HID;
    const float* Crow = g_C + (size_t)b * SEQ * SEQ;
    const int t0 = q * CHUNK;

    float e[64];
#pragma unroll
    for (int t = 0; t < 64; t++) e[t] = err[(size_t)(t0 + t) * HID + i];

    for (int sbk = 0; sbk < q; sbk++) {
        for (int idx = threadIdx.x; idx < 64 * 64; idx += 128) {
            int tt = idx >> 6, ss = idx & 63;
            sC[tt][ss] = Crow[(size_t)(t0 + tt) * SEQ + sbk * 64 + ss];
        }
        __syncthreads();
        for (int s = 0; s < 64; s++) {
            float ev = err[(size_t)(sbk * 64 + s) * HID + i];
#pragma unroll
            for (int t = 0; t < 64; t++) e[t] -= sC[t][s] * ev;
        }
        __syncthreads();
    }

    for (int idx = threadIdx.x; idx < 64 * 64; idx += 128) {
        int tt = idx >> 6, ss = idx & 63;
        sC[tt][ss] = Crow[(size_t)(t0 + tt) * SEQ + t0 + ss];
    }
    __syncthreads();

#pragma unroll
    for (int t = 1; t < 64; t++) {
        float sum = 0.f;
#pragma unroll
        for (int s = 0; s < t; s++) sum += sC[t][s] * e[s];
        e[t] -= sum;
    }
#pragma unroll
    for (int t = 0; t < 64; t++) err[(size_t)(t0 + t) * HID + i] = e[t];
}

// ---------------- act = silu(err + target) -> fp16 ----------------
__global__ void silu_conv() {
    size_t i = ((size_t)blockIdx.x * blockDim.x + threadIdx.x) * 2;
    float2 d = *(const float2*)&g_D[i];
    float2 t = *(const float2*)&g_T[i];
    float v0 = d.x + t.x, v1 = d.y + t.y;
    float s0 = v0 / (1.0f + expf(-v0)), s1 = v1 / (1.0f + expf(-v1));
    __half2 h; h.x = __float2half_rn(s0); h.y = __float2half_rn(s1);
    *(__half2*)&g_ach[i] = h;
}

// ---------------- gate + mix + layernorm ----------------
__global__ __launch_bounds__(256)
void gate_ln(const float* __restrict__ x, const float* __restrict__ gamma,
             const float* __restrict__ beta, float* __restrict__ out) {
    const size_t row = blockIdx.x;
    const float* zr = g_D + row * HID;
    const float* tr = g_TTT + row * HID;
    const float* xr = x + row * HID;

    float y[4];
    float sum = 0.f, sumsq = 0.f;
#pragma unroll
    for (int k = 0; k < 4; k++) {
        int h = threadIdx.x + k * 256;
        float z = zr[h];
        float g = 1.0f / (1.0f + expf(-z));
        float v = g * tr[h] + (1.0f - g) * xr[h];
        y[k] = v;
        sum += v;
        sumsq += v * v;
    }
    __shared__ float sa[8], sbm[8];
#pragma unroll
    for (int o = 16; o > 0; o >>= 1) {
        sum += __shfl_down_sync(0xffffffffu, sum, o);
        sumsq += __shfl_down_sync(0xffffffffu, sumsq, o);
    }
    int w = threadIdx.x >> 5, l = threadIdx.x & 31;
    if (l == 0) { sa[w] = sum; sbm[w] = sumsq; }
    __syncthreads();
    if (w == 0) {
        float a = (l < 8) ? sa[l] : 0.f;
        float bsum = (l < 8) ? sbm[l] : 0.f;
#pragma unroll
        for (int o = 4; o > 0; o >>= 1) {
            a += __shfl_down_sync(0xffu, a, o);
            bsum += __shfl_down_sync(0xffu, bsum, o);
        }
        if (l == 0) { sa[0] = a; sbm[0] = bsum; }
    }
    __syncthreads();
    float mu = sa[0] * (1.0f / HID);
    float var = sbm[0] * (1.0f / HID) - mu * mu;
    float inv = rsqrtf(var + EPS_);
#pragma unroll
    for (int k = 0; k < 4; k++) {
        int h = threadIdx.x + k * 256;
        out[row * HID + h] = (y[k] - mu) * inv * gamma[h] + beta[h];
    }
}

// ---------------------------------------------------------------------------
#define SYMP(T, p, s) T* p; { void* t_; cudaGetSymbolAddress(&t_, s); p = (T*)t_; }

extern "C" void kernel_launch(void* const* d_in, const int* in_sizes, int n_in,
                              void* d_out, int out_size) {
    const float* x      = (const float*)d_in[0];
    const float* W_init = (const float*)d_in[1];
    const float* b_init = (const float*)d_in[2];
    const float* Wt     = (const float*)d_in[3];
    const float* bt     = (const float*)d_in[4];
    const float* Wo     = (const float*)d_in[5];
    const float* bo     = (const float*)d_in[6];
    const float* Wg     = (const float*)d_in[7];
    const float* bg     = (const float*)d_in[8];
    const float* gamma  = (const float*)d_in[9];
    const float* beta   = (const float*)d_in[10];
    float* out = (float*)d_out;

    SYMP(__half, pxh, g_xh);
    SYMP(__half, pah, g_ach);
    SYMP(__half, pth, g_tth);
    SYMP(__half, pwd, g_wd);
    SYMP(__half, pwt, g_wt);
    SYMP(__half, pwo, g_wo);
    SYMP(__half, pwg1, g_wg1);
    SYMP(__half, pwg2, g_wg2);
    SYMP(float, pdb, g_dbias);
    SYMP(float, pD, g_D); SYMP(float, pT, g_T); SYMP(float, pTTT, g_TTT);
    SYMP(float, pC, g_C);

    cudaFuncSetAttribute(tgemm, cudaFuncAttributeMaxDynamicSharedMemorySize, SMEM_BYTES);

    // prep: weight transposes/converts, dbias, x convert
    dim3 wg(32, 32), wb(32, 8);
    wconv<<<wg, wb>>>(W_init, Wt, pwd);
    wconv<<<wg, wb>>>(Wt, nullptr, pwt);
    wconv<<<wg, wb>>>(Wo, nullptr, pwo);
    wconv<<<wg, wb>>>(Wg, nullptr, pwg1);
    wconv<<<wg, wb>>>(Wg + (size_t)HID * HID, nullptr, pwg2);
    dbias_k<<<4, 256>>>(b_init, bt);
    cvt_h<<<(unsigned)(((size_t)MTOT * HID) / 512), 256>>>(x, pxh);

    dim3 gmain(8, 256, 1);
    // 1) D = x @ (W_init - Wt) + (b_init - bt)
    tgemm<<<gmain, 256, SMEM_BYTES>>>(pxh, pwd, 0, 0, pdb, pD,
                                      HID, HID, HID, 0, 0, 0, HID, 0, 0, nullptr);
    // 2) T = x @ Wt + bt
    tgemm<<<gmain, 256, SMEM_BYTES>>>(pxh, pwt, 0, 0, bt, pT,
                                      HID, HID, HID, 0, 0, 0, HID, 0, 0, nullptr);
    // 3) Chat = LRI*(X X^T + 1) per batch (lower tiles only)
    tgemm<<<dim3(4, 4, BATCH), 256, SMEM_BYTES>>>(pxh, pxh, 0, 0, nullptr, pC,
                                      HID, HID, SEQ, (long long)SEQ * HID, (long long)SEQ * HID,
                                      (long long)SEQ * SEQ, HID, 0, 1, nullptr);
    // 4) triangular solve
    for (int q = 0; q < NCHUNK; q++)
        solve_chunk<<<dim3(HID / 128, BATCH), 128>>>(q);
    // 5) act = silu(err + T) -> fp16
    silu_conv<<<(unsigned)(((size_t)MTOT * HID) / 512), 256>>>();
    // 6) ttt = act @ Wo + bo (fp32 + fp16 copy)
    tgemm<<<gmain, 256, SMEM_BYTES>>>(pah, pwo, 0, 0, bo, pTTT,
                                      HID, HID, HID, 0, 0, 0, HID, 0, 0, pth);
    // 7) z = x @ Wg_top + ttt @ Wg_bot + bg (dual-source, K=2048)
    tgemm<<<gmain, 256, SMEM_BYTES>>>(pxh, pwg1, pth, pwg2, bg, pD,
                                      HID, HID, HID, 0, 0, 0, HID, HID, 0, nullptr);
    // 8) gate mix + layernorm
    gate_ln<<<MTOT, 256>>>(x, gamma, beta, out);
}

// round 12
// speedup vs baseline: 4.2521x; 1.2580x over previous
#include <cuda_runtime.h>
#include <cuda_bf16.h>
#include <cuda_fp16.h>
#include <math.h>
#include <stdint.h>

#define BATCH 64
#define SEQ   512
#define HID   1024
#define LRI   (0.01f / 1024.0f)
#define EPS_  1e-5f
#define CHUNK 64
#define NCHUNK (SEQ / CHUNK)
#define MTOT (BATCH * SEQ)

// ---------------- device scratch ----------------
__device__ __half g_xh[(size_t)MTOT * HID];
__device__ __half g_ach[(size_t)MTOT * HID];     // act = silu(err+T) fp16
__device__ __half g_tth[(size_t)MTOT * HID];     // ttt fp16
__device__ __half g_errT[(size_t)BATCH * HID * SEQ]; // err fp16, transposed [b][i][s]
__device__ __half g_Ch[(size_t)BATCH * SEQ * SEQ];   // Chat fp16
__device__ __half g_wd[HID * HID];
__device__ __half g_wt[HID * HID];
__device__ __half g_wo[HID * HID];
__device__ __half g_wg1[HID * HID];
__device__ __half g_wg2[HID * HID];
__device__ float g_dbias[HID];
__device__ float g_D[(size_t)MTOT * HID];   // D, later z
__device__ float g_T[(size_t)MTOT * HID];   // target
__device__ float g_TTT[(size_t)MTOT * HID]; // ttt fp32

// ---------------- PTX helpers (plain sm_80+ features only) ----------------
static __device__ __forceinline__ uint32_t s2u(const void* p) {
    uint32_t a;
    asm("{ .reg .u64 t; cvta.to.shared.u64 t, %1; cvt.u32.u64 %0, t; }" : "=r"(a) : "l"(p));
    return a;
}
#define CPA(dst, src) \
    asm volatile("cp.async.cg.shared.global [%0], [%1], 16;" :: "r"(dst), "l"(src))
#define CPCOMMIT() asm volatile("cp.async.commit_group;" ::: "memory")
#define CPWAIT1()  asm volatile("cp.async.wait_group 1;" ::: "memory")
#define LDSM4(r, addr) \
    asm volatile("ldmatrix.sync.aligned.m8n8.x4.shared.b16 {%0,%1,%2,%3}, [%4];" \
                 : "=r"((r)[0]), "=r"((r)[1]), "=r"((r)[2]), "=r"((r)[3]) : "r"(addr))
#define MMA(c, a, b0, b1) \
    asm volatile("mma.sync.aligned.m16n8k16.row.col.f32.f16.f16.f32 " \
                 "{%0,%1,%2,%3}, {%4,%5,%6,%7}, {%8,%9}, {%0,%1,%2,%3};" \
                 : "+f"((c)[0]), "+f"((c)[1]), "+f"((c)[2]), "+f"((c)[3]) \
                 : "r"((a)[0]), "r"((a)[1]), "r"((a)[2]), "r"((a)[3]), "r"(b0), "r"(b1))

#define BUF_BYTES 10240
#define STG_BYTES (2 * BUF_BYTES)
#define SMEM_BYTES (3 * STG_BYTES)

// ---------------- tensor GEMM: C[m][n] = sum_k A[m][k]*B[n][k] -------------
// mode 0: C = v + bias (K2>0: dual-K source A2/B2 continues accumulation)
// mode 1: gram, Coh = fp16(LRI*(v+1)), skip upper tiles, batched via bz
// mode 2: dual-N: tiles with n0>=HID use weight2 (B2h), bias2, C2
__global__ __launch_bounds__(256, 1)
void tgemm(const __half* __restrict__ Ah, const __half* __restrict__ Bh,
           const __half* __restrict__ A2h, const __half* __restrict__ B2h,
           const float* __restrict__ bias, float* __restrict__ C,
           const float* __restrict__ bias2, float* __restrict__ C2,
           int lda, int ldb, int ldc,
           long long sA, long long sB, long long sC,
           int K1, int K2, int mode,
           __half* __restrict__ Coh) {
    if (mode == 1 && blockIdx.x > blockIdx.y) return;
    extern __shared__ char smem[];
    const uint32_t su = s2u(smem);
    const int tid = threadIdx.x;
    const int wid = tid >> 5, lane = tid & 31;
    const int wm = wid >> 2, wn = wid & 3;          // 2 x 4 warp grid, 64x32 per warp
    const int m0 = blockIdx.y * 128;
    int n0 = blockIdx.x * 128;
    const size_t bz = blockIdx.z;

    const float* biasSel = bias;
    float* Csel = C;
    if (mode == 2 && n0 >= HID) { n0 -= HID; Bh = B2h; biasSel = bias2; Csel = C2; }

    const __half* aH = Ah + bz * sA + (size_t)m0 * lda;
    const __half* bH = Bh + bz * sB + (size_t)n0 * ldb;
    const __half *a2H = nullptr, *b2H = nullptr;
    if (K2) {
        a2H = A2h + (size_t)m0 * lda;
        b2H = B2h + (size_t)n0 * ldb;
    }
    const int nc1 = K1 >> 5;
    const int NC = nc1 + (K2 >> 5);

    uint32_t aoff[4], boff[2];
#pragma unroll
    for (int mi = 0; mi < 4; mi++)
        aoff[mi] = (uint32_t)((wm * 64 + mi * 16 + (lane & 7) + ((lane >> 3) & 1) * 8) * 80
                              + ((lane >> 4) & 1) * 16);
#pragma unroll
    for (int g = 0; g < 2; g++)
        boff[g] = (uint32_t)((wn * 32 + g * 16 + (lane & 7) + ((lane >> 4) & 1) * 8) * 80
                             + ((lane >> 3) & 1) * 16);

    float acc[4][4][4];
#pragma unroll
    for (int i = 0; i < 4; i++)
#pragma unroll
        for (int j = 0; j < 4; j++)
#pragma unroll
            for (int r = 0; r < 4; r++) acc[i][j][r] = 0.f;

    auto load_chunk = [&](int stage, int c) {
        const __half *s0, *s1; int k0;
        if (c < nc1) { s0 = aH; s1 = bH; k0 = c << 5; }
        else         { s0 = a2H; s1 = b2H; k0 = (c - nc1) << 5; }
        const __half* srcs[2] = { s0, s1 };
        const int lds[2] = { lda, ldb };
        const uint32_t d0 = su + stage * STG_BYTES;
#pragma unroll
        for (int it = 0; it < 4; it++) {
            int t = it * 256 + tid;
            int buf = t >> 9, w = t & 511, row = w >> 2, ch = w & 3;
            const __half* g = srcs[buf] + (size_t)row * lds[buf] + k0 + ch * 8;
            CPA(d0 + buf * BUF_BYTES + row * 80 + ch * 16, g);
        }
    };

    load_chunk(0, 0); CPCOMMIT();
    if (NC > 1) load_chunk(1, 1);
    CPCOMMIT();

    for (int c = 0; c < NC; c++) {
        CPWAIT1();
        __syncthreads();
        if (c + 2 < NC) load_chunk((c + 2) % 3, c + 2);
        CPCOMMIT();

        const uint32_t sb0 = su + (c % 3) * STG_BYTES;
#pragma unroll
        for (int kk = 0; kk < 2; kk++) {
            uint32_t ahf[4][4], bhf[2][4];
#pragma unroll
            for (int mi = 0; mi < 4; mi++)
                LDSM4(ahf[mi], sb0 + aoff[mi] + kk * 32);
#pragma unroll
            for (int g = 0; g < 2; g++)
                LDSM4(bhf[g], sb0 + BUF_BYTES + boff[g] + kk * 32);
#pragma unroll
            for (int mi = 0; mi < 4; mi++)
#pragma unroll
                for (int nj = 0; nj < 4; nj++) {
                    const int g = nj >> 1, h = (nj & 1) * 2;
                    MMA(acc[mi][nj], ahf[mi], bhf[g][h], bhf[g][h + 1]);
                }
        }
    }

    // epilogue
    float* Cb = Csel ? Csel + bz * sC : nullptr;
    __half* Cho = Coh ? Coh + bz * sC : nullptr;
    const int g4 = lane >> 2, tg = (lane & 3) * 2;
#pragma unroll
    for (int mi = 0; mi < 4; mi++)
#pragma unroll
        for (int nj = 0; nj < 4; nj++) {
            const int col = n0 + wn * 32 + nj * 8 + tg;
            float bv0 = 0.f, bv1 = 0.f;
            if (mode != 1 && biasSel) { bv0 = biasSel[col]; bv1 = biasSel[col + 1]; }
#pragma unroll
            for (int half_ = 0; half_ < 2; half_++) {
                const int row = m0 + wm * 64 + mi * 16 + g4 + half_ * 8;
                float v0 = acc[mi][nj][half_ * 2], v1 = acc[mi][nj][half_ * 2 + 1];
                const size_t gi = (size_t)row * ldc + col;
                if (mode == 1) {
                    v0 = LRI * (v0 + 1.f); v1 = LRI * (v1 + 1.f);
                    __half2 hp; hp.x = __float2half_rn(v0); hp.y = __float2half_rn(v1);
                    *(__half2*)&Cho[gi] = hp;
                } else {
                    v0 += bv0; v1 += bv1;
                    *(float2*)&Cb[gi] = make_float2(v0, v1);
                    if (Cho) {
                        __half2 hp; hp.x = __float2half_rn(v0); hp.y = __float2half_rn(v1);
                        *(__half2*)&Cho[gi] = hp;
                    }
                }
            }
        }
}

// ---------------- prep kernels ----------------
__global__ void wconv(const float* __restrict__ W, const float* __restrict__ Wsub,
                      __half* __restrict__ oh) {
    __shared__ float t[32][33];
    int bx = blockIdx.x * 32, by = blockIdx.y * 32;
    int tx = threadIdx.x, ty = threadIdx.y;
    for (int i = ty; i < 32; i += 8) {
        float v = W[(size_t)(by + i) * HID + bx + tx];
        if (Wsub) v -= Wsub[(size_t)(by + i) * HID + bx + tx];
        t[i][tx] = v;
    }
    __syncthreads();
    for (int i = ty; i < 32; i += 8)
        oh[(size_t)(bx + i) * HID + by + tx] = __float2half_rn(t[tx][i]);
}

__global__ void cvt_h(const float* __restrict__ in, __half* __restrict__ oh) {
    size_t i = ((size_t)blockIdx.x * blockDim.x + threadIdx.x) * 2;
    float2 v = *(const float2*)&in[i];
    __half2 h; h.x = __float2half_rn(v.x); h.y = __float2half_rn(v.y);
    *(__half2*)&oh[i] = h;
}

__global__ void dbias_k(const float* __restrict__ bi, const float* __restrict__ bt) {
    int i = blockIdx.x * 256 + threadIdx.x;
    if (i < HID) g_dbias[i] = bi[i] - bt[i];
}

// ---------------- solve2: tensor-core history + fp32 diagonal + fused silu --
// grid (HID/128, BATCH), 128 threads. Chunk q of 64 t-steps.
// history: corr[t][i] = sum_{s<t0} Chat[t][s] * err[s][i]  via mma (fp16 in, fp32 acc)
// diag:    e[t] = D[t][i] - corr - strict-lower recurrence (fp32)
// epilogue: act = silu(e + T) fp16 ; errT[i][t] = fp16(e)
#define SOLVE_SMEM 49152
__global__ __launch_bounds__(128)
void solve2(int q) {
    extern __shared__ char sm[];
    const int b = blockIdx.y;
    const int i0 = blockIdx.x * 128;
    const int t0 = q * CHUNK;
    const int tid = threadIdx.x;
    const int wid = tid >> 5, lane = tid & 31;

    const __half* Ch = g_Ch + (size_t)b * SEQ * SEQ;
    const __half* errT = g_errT + (size_t)b * HID * SEQ;

    // ---- history phase (mma) ----
    __half* sA = (__half*)sm;            // 64 x 72 halfs (144B rows)
    __half* sB = (__half*)(sm + 9216);   // 128 x 72 halfs
    const uint32_t suA = s2u(sA), suB = s2u(sB);

    float acc[4][4][4];
#pragma unroll
    for (int mi = 0; mi < 4; mi++)
#pragma unroll
        for (int nj = 0; nj < 4; nj++)
#pragma unroll
            for (int r = 0; r < 4; r++) acc[mi][nj][r] = 0.f;

    uint32_t aoff[4], boff[2];
#pragma unroll
    for (int mi = 0; mi < 4; mi++)
        aoff[mi] = (uint32_t)((mi * 16 + (lane & 7) + ((lane >> 3) & 1) * 8) * 144
                              + ((lane >> 4) & 1) * 16);
#pragma unroll
    for (int g = 0; g < 2; g++)
        boff[g] = (uint32_t)((wid * 32 + g * 16 + (lane & 7) + ((lane >> 4) & 1) * 8) * 144
                             + ((lane >> 3) & 1) * 16);

    for (int sb = 0; sb < q; sb++) {
        // load Chat tile 64x64 (A) and errT tile 128x64 (B)
#pragma unroll
        for (int it = 0; it < 4; it++) {
            int c = it * 128 + tid;
            int row = c >> 3, ch = c & 7;
            *(uint4*)(sA + row * 72 + ch * 8) =
                *(const uint4*)(Ch + (size_t)(t0 + row) * SEQ + sb * 64 + ch * 8);
        }
#pragma unroll
        for (int it = 0; it < 8; it++) {
            int c = it * 128 + tid;
            int row = c >> 3, ch = c & 7;
            *(uint4*)(sB + row * 72 + ch * 8) =
                *(const uint4*)(errT + (size_t)(i0 + row) * SEQ + sb * 64 + ch * 8);
        }
        __syncthreads();
#pragma unroll
        for (int kk = 0; kk < 4; kk++) {
            uint32_t ahf[4][4], bhf[2][4];
#pragma unroll
            for (int mi = 0; mi < 4; mi++)
                LDSM4(ahf[mi], suA + aoff[mi] + kk * 32);
#pragma unroll
            for (int g = 0; g < 2; g++)
                LDSM4(bhf[g], suB + boff[g] + kk * 32);
#pragma unroll
            for (int mi = 0; mi < 4; mi++)
#pragma unroll
                for (int nj = 0; nj < 4; nj++) {
                    const int g = nj >> 1, h = (nj & 1) * 2;
                    MMA(acc[mi][nj], ahf[mi], bhf[g][h], bhf[g][h + 1]);
                }
        }
        __syncthreads();
    }

    // ---- dump correction to smem (full 64x128 coverage across 4 warps) ----
    float* corr = (float*)sm;                 // 64 x 128 fp32
    float* sDg = (float*)(sm + 32768);        // 64 x 64 fp32 diag
    const int g4 = lane >> 2, tg = (lane & 3) * 2;
#pragma unroll
    for (int mi = 0; mi < 4; mi++)
#pragma unroll
        for (int nj = 0; nj < 4; nj++) {
            const int col = wid * 32 + nj * 8 + tg;
#pragma unroll
            for (int half_ = 0; half_ < 2; half_++) {
                const int row = mi * 16 + g4 + half_ * 8;
                corr[row * 128 + col] = acc[mi][nj][half_ * 2];
                corr[row * 128 + col + 1] = acc[mi][nj][half_ * 2 + 1];
            }
        }
    // load diagonal block fp16 -> fp32
#pragma unroll
    for (int it = 0; it < 32; it++) {
        int c = it * 128 + tid;
        int row = c >> 6, s = c & 63;
        sDg[row * 64 + s] = __half2float(Ch[(size_t)(t0 + row) * SEQ + t0 + s]);
    }
    __syncthreads();

    // ---- diagonal recurrence (fp32) + fused silu epilogue ----
    const int i = i0 + tid;
    const float* Drow = g_D + (size_t)b * SEQ * HID + i;
    const float* Trow = g_T + (size_t)b * SEQ * HID + i;
    __half* arow = g_ach + (size_t)b * SEQ * HID + i;
    __half* eT = g_errT + (size_t)b * HID * SEQ + (size_t)i * SEQ + t0;

    float e[64];
#pragma unroll
    for (int t = 0; t < 64; t++)
        e[t] = Drow[(size_t)(t0 + t) * HID] - corr[t * 128 + tid];

#pragma unroll
    for (int t = 1; t < 64; t++) {
        float sum = 0.f;
#pragma unroll
        for (int s = 0; s < t; s++) sum += sDg[t * 64 + s] * e[s];
        e[t] -= sum;
    }

    const bool last = (q == NCHUNK - 1);
#pragma unroll
    for (int t = 0; t < 64; t++) {
        float inner = e[t] + Trow[(size_t)(t0 + t) * HID];
        float s = inner / (1.0f + expf(-inner));
        arow[(size_t)(t0 + t) * HID] = __float2half_rn(s);
        if (!last) eT[t] = __float2half_rn(e[t]);
    }
}

// ---------------- gate + mix + layernorm ----------------
__global__ __launch_bounds__(256)
void gate_ln(const float* __restrict__ x, const float* __restrict__ gamma,
             const float* __restrict__ beta, float* __restrict__ out) {
    const size_t row = blockIdx.x;
    const float* zr = g_D + row * HID;
    const float* tr = g_TTT + row * HID;
    const float* xr = x + row * HID;

    float y[4];
    float sum = 0.f, sumsq = 0.f;
#pragma unroll
    for (int k = 0; k < 4; k++) {
        int h = threadIdx.x + k * 256;
        float z = zr[h];
        float g = 1.0f / (1.0f + expf(-z));
        float v = g * tr[h] + (1.0f - g) * xr[h];
        y[k] = v;
        sum += v;
        sumsq += v * v;
    }
    __shared__ float sa[8], sbm[8];
#pragma unroll
    for (int o = 16; o > 0; o >>= 1) {
        sum += __shfl_down_sync(0xffffffffu, sum, o);
        sumsq += __shfl_down_sync(0xffffffffu, sumsq, o);
    }
    int w = threadIdx.x >> 5, l = threadIdx.x & 31;
    if (l == 0) { sa[w] = sum; sbm[w] = sumsq; }
    __syncthreads();
    if (w == 0) {
        float a = (l < 8) ? sa[l] : 0.f;
        float bsum = (l < 8) ? sbm[l] : 0.f;
#pragma unroll
        for (int o = 4; o > 0; o >>= 1) {
            a += __shfl_down_sync(0xffu, a, o);
            bsum += __shfl_down_sync(0xffu, bsum, o);
        }
        if (l == 0) { sa[0] = a; sbm[0] = bsum; }
    }
    __syncthreads();
    float mu = sa[0] * (1.0f / HID);
    float var = sbm[0] * (1.0f / HID) - mu * mu;
    float inv = rsqrtf(var + EPS_);
#pragma unroll
    for (int k = 0; k < 4; k++) {
        int h = threadIdx.x + k * 256;
        out[row * HID + h] = (y[k] - mu) * inv * gamma[h] + beta[h];
    }
}

// ---------------------------------------------------------------------------
#define SYMP(T, p, s) T* p; { void* t_; cudaGetSymbolAddress(&t_, s); p = (T*)t_; }

extern "C" void kernel_launch(void* const* d_in, const int* in_sizes, int n_in,
                              void* d_out, int out_size) {
    const float* x      = (const float*)d_in[0];
    const float* W_init = (const float*)d_in[1];
    const float* b_init = (const float*)d_in[2];
    const float* Wt     = (const float*)d_in[3];
    const float* bt     = (const float*)d_in[4];
    const float* Wo     = (const float*)d_in[5];
    const float* bo     = (const float*)d_in[6];
    const float* Wg     = (const float*)d_in[7];
    const float* bg     = (const float*)d_in[8];
    const float* gamma  = (const float*)d_in[9];
    const float* beta   = (const float*)d_in[10];
    float* out = (float*)d_out;

    SYMP(__half, pxh, g_xh);
    SYMP(__half, pah, g_ach);
    SYMP(__half, pth, g_tth);
    SYMP(__half, pCh, g_Ch);
    SYMP(__half, pwd, g_wd);
    SYMP(__half, pwt, g_wt);
    SYMP(__half, pwo, g_wo);
    SYMP(__half, pwg1, g_wg1);
    SYMP(__half, pwg2, g_wg2);
    SYMP(float, pdb, g_dbias);
    SYMP(float, pD, g_D); SYMP(float, pT, g_T); SYMP(float, pTTT, g_TTT);

    cudaFuncSetAttribute(tgemm, cudaFuncAttributeMaxDynamicSharedMemorySize, SMEM_BYTES);
    cudaFuncSetAttribute(solve2, cudaFuncAttributeMaxDynamicSharedMemorySize, SOLVE_SMEM);

    // prep
    dim3 wg(32, 32), wb(32, 8);
    wconv<<<wg, wb>>>(W_init, Wt, pwd);
    wconv<<<wg, wb>>>(Wt, nullptr, pwt);
    wconv<<<wg, wb>>>(Wo, nullptr, pwo);
    wconv<<<wg, wb>>>(Wg, nullptr, pwg1);
    wconv<<<wg, wb>>>(Wg + (size_t)HID * HID, nullptr, pwg2);
    dbias_k<<<4, 256>>>(b_init, bt);
    cvt_h<<<(unsigned)(((size_t)MTOT * HID) / 512), 256>>>(x, pxh);

    // 1+2) merged: D = x@Wd + dbias (cols 0-1023), T = x@Wt + bt (cols 1024-2047)
    tgemm<<<dim3(16, 256, 1), 256, SMEM_BYTES>>>(pxh, pwd, nullptr, pwt, pdb, pD,
                                      bt, pT,
                                      HID, HID, HID, 0, 0, 0, HID, 0, 2, nullptr);
    // 3) Chat = fp16(LRI*(X X^T + 1)) per batch (lower tiles only)
    tgemm<<<dim3(4, 4, BATCH), 256, SMEM_BYTES>>>(pxh, pxh, nullptr, nullptr, nullptr, nullptr,
                                      nullptr, nullptr,
                                      HID, HID, SEQ, (long long)SEQ * HID, (long long)SEQ * HID,
                                      (long long)SEQ * SEQ, HID, 0, 1, pCh);
    // 4) chunked solve (tensor history + fp32 diag + fused silu)
    for (int q = 0; q < NCHUNK; q++)
        solve2<<<dim3(HID / 128, BATCH), 128, SOLVE_SMEM>>>(q);
    // 5) ttt = act @ Wo + bo (fp32 + fp16 copy)
    tgemm<<<dim3(8, 256, 1), 256, SMEM_BYTES>>>(pah, pwo, nullptr, nullptr, bo, pTTT,
                                      nullptr, nullptr,
                                      HID, HID, HID, 0, 0, 0, HID, 0, 0, pth);
    // 6) z = x @ Wg_top + ttt @ Wg_bot + bg (dual-K, K=2048)
    tgemm<<<dim3(8, 256, 1), 256, SMEM_BYTES>>>(pxh, pwg1, pth, pwg2, bg, pD,
                                      nullptr, nullptr,
                                      HID, HID, HID, 0, 0, 0, HID, HID, 0, nullptr);
    // 7) gate mix + layernorm
    gate_ln<<<MTOT, 256>>>(x, gamma, beta, out);
}